// round 16
// baseline (speedup 1.0000x reference)
#include <cuda_runtime.h>
#include <cuda_bf16.h>
#include <cstdint>
#include <cstddef>

// ============================================================================
// RNN_4715874091371 — GB300 sm_103a (compute_103 PTX)
//   Z = X @ W_ih^T + (b_ih+b_hh)   bf16 GEMM 128x128/2CTA/warp 64x32,
//       GROUP-PRIVATE rings (A per wm-half, B per wn-quad), narrow barriers,
//       zero CTA-wide syncs in mainloop
//   h_t = tanh(Z_t + h_{t-1} @ W_hh^T)  persistent bf16 kernel, 128 CTAs,
//       CTA 128x64, W_hh resident, warp 32x32, fully pair-decoupled chains
//   p = sigmoid(h @ W_out^T + b_out);  loss = BCE(p, y >= 1e-5)
// ============================================================================

static constexpr int TT = 64;
static constexpr int BB = 1024;
static constexpr int HH = 1024;

// ---------------- device scratch (allocation-free rule) --------------------
__device__ __nv_bfloat16 g_Xbf[(size_t)BB * TT * HH];    // av in bf16 (128MB)
__device__ __nv_bfloat16 g_Wihbf[(size_t)HH * HH];       // W_ih bf16
__device__ __nv_bfloat16 g_Whhbf[(size_t)HH * HH];       // W_hh bf16
__device__ float g_Z[(size_t)TT * BB * HH];               // [t][b][h] fp32
__device__ __nv_bfloat16 g_hbf[2][(size_t)BB * HH];       // ping-pong hidden
__device__ float g_p[BB];
__device__ unsigned g_pbars[8][4];                         // per-(group,pair)

#define DEVI __device__ __forceinline__

DEVI uint32_t smem_u32(const void* p) {
    uint32_t a;
    asm("{ .reg .u64 t; cvta.to.shared.u64 t, %1; cvt.u32.u64 %0, t; }"
        : "=r"(a) : "l"(p));
    return a;
}

#define CPA16(dst_b, src) \
    asm volatile("cp.async.cg.shared.global [%0], [%1], 16;" :: "r"(dst_b), "l"(src))
#define CPC()    asm volatile("cp.async.commit_group;" ::: "memory")
#define CPW1()   asm volatile("cp.async.wait_group 1;" ::: "memory")
#define CPW2()   asm volatile("cp.async.wait_group 2;" ::: "memory")
#define CPWALL() asm volatile("cp.async.wait_all;" ::: "memory")
#define BAR64(id)  asm volatile("bar.sync %0, 64;"  :: "r"(id) : "memory")
#define BAR128(id) asm volatile("bar.sync %0, 128;" :: "r"(id) : "memory")

// bf16 m16n8k16: D += A*B
#define MMA_BF16(d, a, b)                                                       \
    asm("mma.sync.aligned.m16n8k16.row.col.f32.bf16.bf16.f32 "                  \
        "{%0,%1,%2,%3}, {%4,%5,%6,%7}, {%8,%9}, {%0,%1,%2,%3};"                 \
        : "+f"((d)[0]), "+f"((d)[1]), "+f"((d)[2]), "+f"((d)[3])                \
        : "r"((a)[0]), "r"((a)[1]), "r"((a)[2]), "r"((a)[3]),                   \
          "r"((b)[0]), "r"((b)[1]))

// ldmatrix x4: d[0..3] <- four 8x8 b16 matrices
#define LDSM4(d, addr)                                                          \
    asm volatile("ldmatrix.sync.aligned.m8n8.x4.shared.b16 {%0,%1,%2,%3}, [%4];"\
        : "=r"((d)[0]), "=r"((d)[1]), "=r"((d)[2]), "=r"((d)[3]) : "r"(addr))

// ============================================================================
// Big GEMM (bf16): Z = Xbf @ Wihbf^T + (b_ih+b_hh). CTA tile 128x128,
// warp grid 2(wm) x 4(wn), warp tile 64x32. K-chunk 64 halves, 16 chunks.
// GROUP-PRIVATE 3-stage rings:
//   A ring per wm-half (64 rows), loaded+synced by its 4 contiguous warps
//   B ring per wn-quad (32 rows), loaded+synced by its 2 warps (wm=0,1)
// One narrow bar.sync per ring per chunk; no CTA-wide sync in mainloop.
// 2 CTAs/SM, ldmatrix. grid(x = 8 n-tiles, y = 512 m-tiles).
// ============================================================================
__global__ __launch_bounds__(256, 2)
void gemm_big(const float* __restrict__ bih, const float* __restrict__ bhh)
{
    constexpr int ASTG = 64 * 36;                  // words per A stage
    constexpr int BSTG = 32 * 36;                  // words per B stage
    constexpr int ATOT = 2 * 3 * ASTG;             // 2 halves x 3 stages
    extern __shared__ __align__(16) uint32_t sm[];
    const uint32_t smb = smem_u32(sm);

    const int tid  = threadIdx.x;
    const int lane = tid & 31;
    const int wid  = tid >> 5;
    const int wm   = wid >> 2;             // A half 0/1 (warps contiguous)
    const int wn   = wid & 3;              // B quad 0..3
    const int at   = tid & 127;            // thread index within A group
    const int bt   = lane + wm * 32;       // thread index within B group
    const int n0   = blockIdx.x * 128;
    const int m0   = blockIdx.y * 128;

    const int lrA = lane & 15;
    const int whA = (lane >> 4) * 4;
    const int lrB = (lane & 7) | ((lane >> 4) << 3);
    const int wB  = ((lane >> 3) & 1) * 4;

    const uint32_t aring = smb + (uint32_t)(wm * 3 * ASTG) * 4;
    const uint32_t bring = smb + (uint32_t)(ATOT + wn * 3 * BSTG) * 4;

    auto load_A = [&](int c, int s) {               // 64 rows x 128B, 128 thr
        const int kf = c * 64;
        const uint32_t ab = aring + (uint32_t)(s * ASTG) * 4;
        #pragma unroll
        for (int i = 0; i < 4; ++i) {
            int e = at + i * 128, r = e >> 3, j = e & 7;
            CPA16(ab + (uint32_t)(r * 36 + j * 4) * 4,
                  g_Xbf + (size_t)(m0 + wm * 64 + r) * HH + kf + j * 8);
        }
    };
    auto load_B = [&](int c, int s) {               // 32 rows x 128B, 64 thr
        const int kf = c * 64;
        const uint32_t bb = bring + (uint32_t)(s * BSTG) * 4;
        #pragma unroll
        for (int i = 0; i < 4; ++i) {
            int e = bt + i * 64, r = e >> 3, j = e & 7;
            CPA16(bb + (uint32_t)(r * 36 + j * 4) * 4,
                  g_Wihbf + (size_t)(n0 + wn * 32 + r) * HH + kf + j * 8);
        }
    };

    // prologue: chunks 0,1 -> slots 0,1 (one commit group per chunk)
    #pragma unroll
    for (int c = 0; c < 2; ++c) { load_A(c, c); load_B(c, c); CPC(); }

    float acc[4][4][4];
    #pragma unroll
    for (int mi = 0; mi < 4; ++mi)
        #pragma unroll
        for (int nf = 0; nf < 4; ++nf)
            #pragma unroll
            for (int j = 0; j < 4; ++j) acc[mi][nf][j] = 0.f;

    for (int c = 0; c < 16; ++c) {
        CPW1();                            // group c landed (<=1 pending)
        BAR128(1 + wm);                    // A co-readers done with c-1
        BAR64(3 + wn);                     // B co-readers done with c-1
        if (c + 2 < 16) { load_A(c + 2, (c + 2) % 3); load_B(c + 2, (c + 2) % 3); }
        CPC();                             // uniform group count
        const uint32_t sA = aring + (uint32_t)((c % 3) * ASTG) * 4;
        const uint32_t sB = bring + (uint32_t)((c % 3) * BSTG) * 4;
        #pragma unroll
        for (int ks = 0; ks < 4; ++ks) {                     // k16 per MMA
            uint32_t a[4][4];
            #pragma unroll
            for (int mi = 0; mi < 4; ++mi)
                LDSM4(a[mi], sA + (uint32_t)((mi * 16 + lrA) * 36
                                             + ks * 8 + whA) * 4);
            uint32_t b[4][2];
            #pragma unroll
            for (int nfp = 0; nfp < 2; ++nfp)
                LDSM4((&b[2 * nfp][0]),
                      sB + (uint32_t)((nfp * 16 + lrB) * 36
                                      + ks * 8 + wB) * 4);
            #pragma unroll
            for (int mi = 0; mi < 4; ++mi)
                #pragma unroll
                for (int nf = 0; nf < 4; ++nf)
                    MMA_BF16(acc[mi][nf], a[mi], b[nf]);
        }
    }

    // epilogue: + biases, scatter to g_Z[t][b][n]  (m = b*64 + t)
    const int arow = lane >> 2, q = lane & 3;
    #pragma unroll
    for (int mi = 0; mi < 4; ++mi) {
        const int r0 = m0 + wm * 64 + mi * 16 + arow;
        #pragma unroll
        for (int nf = 0; nf < 4; ++nf) {
            const int cg = n0 + wn * 32 + nf * 8 + q * 2;
            const float bsum0 = bih[cg] + bhh[cg];
            const float bsum1 = bih[cg + 1] + bhh[cg + 1];
            #pragma unroll
            for (int half = 0; half < 2; ++half) {
                const int r = r0 + half * 8;
                float2 o;
                o.x = acc[mi][nf][half * 2 + 0] + bsum0;
                o.y = acc[mi][nf][half * 2 + 1] + bsum1;
                const int b = r >> 6, t = r & 63;
                *(float2*)(g_Z + ((size_t)t * BB + b) * HH + cg) = o;
            }
        }
    }
}

// ============================================================================
// Persistent steps (bf16): 128 CTAs (8 m-groups x 16 n-tiles), CTA 128x64,
// warp grid 4x2 (warp tile 32x32). W_hh resident in smem. Four warp PAIRS
// (wm) each own: a private 4-stage A ring, a named pair barrier, and a
// per-(group,pair) flag chain — fully independent across the recurrence.
// ============================================================================
__global__ __launch_bounds__(256, 1)
void steps_k()
{
    constexpr int APST = 32 * 36;                  // words per pair A stage
    constexpr int BOFF = 4 * 4 * APST;             // B base: 4 pairs x 4 stages
    constexpr int RSB  = 516;                      // B row stride (words)
    extern __shared__ __align__(16) uint32_t sm[];
    const uint32_t smb = smem_u32(sm);

    const int tid  = threadIdx.x;
    const int lane = tid & 31;
    const int wid  = tid >> 5;
    const int wm   = wid >> 1;             // pair id 0..3; warp tile 32x32
    const int wn   = wid & 1;
    const int pt   = tid & 63;             // pair-local thread 0..63
    const int mg   = blockIdx.x >> 4;      // m-group 0..7
    const int m0   = mg * 128;
    const int n0   = (blockIdx.x & 15) * 64;
    const uint32_t pbase = smb + (uint32_t)(wm * 4 * APST) * 4;
    unsigned* const myflag = &g_pbars[mg][wm];

    // ---- load resident B = W_hh rows n0..n0+63, full K (CTA-wide) ----
    #pragma unroll
    for (int i = 0; i < 32; ++i) {
        int e = tid + i * 256, r = e >> 7, j = e & 127;
        CPA16(smb + (uint32_t)(BOFF + r * RSB + j * 4) * 4,
              g_Whhbf + (size_t)(n0 + r) * HH + j * 8);
    }
    CPC();
    CPWALL();
    __syncthreads();                       // one-time: B resident for all pairs

    // ---- t = 0: h0 = tanh(Z_0) on this pair's band (32 x 64) ----
    for (int e = pt; e < 32 * 64; e += 64) {
        int r = e >> 6, c = e & 63;
        size_t idx = (size_t)(m0 + wm * 32 + r) * HH + n0 + c;
        g_hbf[0][idx] = __float2bfloat16_rn(tanhf(g_Z[idx]));
    }
    BAR64(1 + wm);
    if (pt == 0) { __threadfence(); atomicAdd(myflag, 1); }

    const int arow = lane >> 2, q = lane & 3;
    const int lrA = lane & 15;
    const int whA = (lane >> 4) * 4;
    const int lrB = (lane & 7) | ((lane >> 4) << 3);
    const int wB  = ((lane >> 3) & 1) * 4;

    for (int t = 1; t < TT; ++t) {
        const __nv_bfloat16* __restrict__ Asrc = g_hbf[(t - 1) & 1];
        __nv_bfloat16*       __restrict__ out  = g_hbf[t & 1];
        const float*         __restrict__ Zt   = g_Z + (size_t)t * BB * HH;

        // Z prefetch (independent of h): hide behind flag wait
        float2 zf[2][4][2];
        #pragma unroll
        for (int mi = 0; mi < 2; ++mi)
            #pragma unroll
            for (int nf = 0; nf < 4; ++nf) {
                const int cg = n0 + wn * 32 + nf * 8 + q * 2;
                #pragma unroll
                for (int half = 0; half < 2; ++half) {
                    const int r = m0 + wm * 32 + mi * 16 + arow + half * 8;
                    zf[mi][nf][half] = *(const float2*)(Zt + (size_t)r * HH + cg);
                }
            }

        // per-(group,pair) chain: 16 CTA-pairs wrote this band of h_{t-1}
        if (pt == 0) {
            const unsigned tgt = 16u * (unsigned)t;
            while (*(volatile unsigned*)myflag < tgt) __nanosleep(32);
            __threadfence();
        }
        BAR64(1 + wm);

        // pair A stage loader: chunk c (64 halves) of this pair's 32 rows
        auto load_stage = [&](int c, int s) {
            const int kf = c * 64;
            const uint32_t ab = pbase + (uint32_t)(s * APST) * 4;
            #pragma unroll
            for (int i = 0; i < 4; ++i) {                    // 32 rows x 128B
                int e = pt + i * 64, r = e >> 3, j = e & 7;
                CPA16(ab + (uint32_t)(r * 36 + j * 4) * 4,
                      Asrc + (size_t)(m0 + wm * 32 + r) * HH + kf + j * 8);
            }
        };

        #pragma unroll
        for (int c = 0; c < 3; ++c) { load_stage(c, c); CPC(); }

        float acc[2][4][4];
        #pragma unroll
        for (int mi = 0; mi < 2; ++mi)
            #pragma unroll
            for (int nf = 0; nf < 4; ++nf)
                #pragma unroll
                for (int j = 0; j < 4; ++j) acc[mi][nf][j] = 0.f;

        for (int c = 0; c < 16; ++c) {
            CPW2();                       // own chunk c landed
            BAR64(1 + wm);                // pair: both warps done with old slot
            if (c + 3 < 16) load_stage(c + 3, (c + 3) & 3);
            CPC();
            const uint32_t sA = pbase + (uint32_t)((c & 3) * APST) * 4;
            #pragma unroll
            for (int ks = 0; ks < 4; ++ks) {                 // k16 per MMA
                uint32_t a[2][4];
                #pragma unroll
                for (int mi = 0; mi < 2; ++mi)
                    LDSM4(a[mi], sA + (uint32_t)((mi * 16 + lrA) * 36
                                                 + ks * 8 + whA) * 4);
                uint32_t b[4][2];
                #pragma unroll
                for (int nfp = 0; nfp < 2; ++nfp)
                    LDSM4((&b[2 * nfp][0]),
                          smb + (uint32_t)(BOFF
                                + (wn * 32 + nfp * 16 + lrB) * RSB
                                + c * 32 + ks * 8 + wB) * 4);
                #pragma unroll
                for (int mi = 0; mi < 2; ++mi)
                    #pragma unroll
                    for (int nf = 0; nf < 4; ++nf)
                        MMA_BF16(acc[mi][nf], a[mi], b[nf]);
            }
        }

        // epilogue: tanh(acc + Z_t) -> bf16 h[t&1] (own band only)
        #pragma unroll
        for (int mi = 0; mi < 2; ++mi)
            #pragma unroll
            for (int nf = 0; nf < 4; ++nf) {
                const int cg = n0 + wn * 32 + nf * 8 + q * 2;
                #pragma unroll
                for (int half = 0; half < 2; ++half) {
                    const int r = m0 + wm * 32 + mi * 16 + arow + half * 8;
                    float ox = tanhf(acc[mi][nf][half * 2 + 0] + zf[mi][nf][half].x);
                    float oy = tanhf(acc[mi][nf][half * 2 + 1] + zf[mi][nf][half].y);
                    __nv_bfloat162 o2 = __floats2bfloat162_rn(ox, oy);
                    *(__nv_bfloat162*)(out + (size_t)r * HH + cg) = o2;
                }
            }
        BAR64(1 + wm);
        if (pt == 0) { __threadfence(); atomicAdd(myflag, 1); }
    }
}

// ----------------------------- small kernels --------------------------------
__global__ void conv_av_k(const float4* __restrict__ av, int n8) {
    int i = blockIdx.x * blockDim.x + threadIdx.x;       // 8 floats per thread
    if (i < n8) {
        float4 a = av[2 * i], b = av[2 * i + 1];
        __nv_bfloat162 p0 = __floats2bfloat162_rn(a.x, a.y);
        __nv_bfloat162 p1 = __floats2bfloat162_rn(a.z, a.w);
        __nv_bfloat162 p2 = __floats2bfloat162_rn(b.x, b.y);
        __nv_bfloat162 p3 = __floats2bfloat162_rn(b.z, b.w);
        uint4 o = make_uint4(*(uint32_t*)&p0, *(uint32_t*)&p1,
                             *(uint32_t*)&p2, *(uint32_t*)&p3);
        ((uint4*)g_Xbf)[i] = o;
    }
}

__global__ void conv_W_k(const float4* __restrict__ wih,
                         const float4* __restrict__ whh, int n4) {
    int i = blockIdx.x * blockDim.x + threadIdx.x;
    if (i < 32) ((unsigned*)g_pbars)[i] = 0;              // reset flag chains
    if (i < n4) {
        float4 a = wih[i];
        __nv_bfloat162 p0 = __floats2bfloat162_rn(a.x, a.y);
        __nv_bfloat162 p1 = __floats2bfloat162_rn(a.z, a.w);
        ((uint2*)g_Wihbf)[i] = make_uint2(*(uint32_t*)&p0, *(uint32_t*)&p1);
        float4 b = whh[i];
        __nv_bfloat162 q0 = __floats2bfloat162_rn(b.x, b.y);
        __nv_bfloat162 q1 = __floats2bfloat162_rn(b.z, b.w);
        ((uint2*)g_Whhbf)[i] = make_uint2(*(uint32_t*)&q0, *(uint32_t*)&q1);
    }
}

__global__ void head_k(const float* __restrict__ Wout,
                       const float* __restrict__ bout) {
    int wid = threadIdx.x >> 5, lane = threadIdx.x & 31;
    int row = blockIdx.x * 8 + wid;
    const __nv_bfloat162* hr =
        (const __nv_bfloat162*)(g_hbf[1] + (size_t)row * HH);
    const float2* wr = (const float2*)Wout;
    float s = 0.f;
    for (int i = lane; i < HH / 2; i += 32) {
        float2 hv = __bfloat1622float2(hr[i]);
        float2 wv = wr[i];
        s += hv.x * wv.x + hv.y * wv.y;
    }
    #pragma unroll
    for (int o = 16; o; o >>= 1) s += __shfl_xor_sync(0xFFFFFFFFu, s, o);
    if (lane == 0) g_p[row] = 1.f / (1.f + expf(-(s + bout[0])));
}

__global__ void loss_k(const float* __restrict__ y, float* __restrict__ out,
                       int out_size) {
    __shared__ float red[32];
    int tid = threadIdx.x;                                // 1024 threads
    float pv = g_p[tid];
    float yb = (y[tid] >= 1e-5f) ? 1.f : 0.f;
    float term = yb * fmaxf(logf(pv), -100.f)
               + (1.f - yb) * fmaxf(log1pf(-pv), -100.f);
    #pragma unroll
    for (int o = 16; o; o >>= 1) term += __shfl_xor_sync(0xFFFFFFFFu, term, o);
    if ((tid & 31) == 0) red[tid >> 5] = term;
    __syncthreads();
    if (tid < 32) {
        float v = red[tid];
        #pragma unroll
        for (int o = 16; o; o >>= 1) v += __shfl_xor_sync(0xFFFFFFFFu, v, o);
        if (tid == 0 && out_size != BB) out[0] = -v / (float)BB;
    }
    if (out_size >= 1 + BB)      out[1 + tid] = pv;
    else if (out_size == BB)     out[tid] = pv;
    for (int i = 1 + BB + tid; i < out_size; i += BB) out[i] = 0.f;
}

// ------------------------------- launcher -----------------------------------
extern "C" void kernel_launch(void* const* d_in, const int* in_sizes, int n_in,
                              void* d_out, int out_size) {
    const float* av   = (const float*)d_in[3];
    const float* y    = (const float*)d_in[4];
    const float* Wih  = (const float*)d_in[5];
    const float* bih  = (const float*)d_in[6];
    const float* Whh  = (const float*)d_in[7];
    const float* bhh  = (const float*)d_in[8];
    const float* Wout = (const float*)d_in[9];
    const float* bout = (const float*)d_in[10];
    (void)in_sizes; (void)n_in;

    constexpr int SMEM_BIG  = (2 * 3 * 64 * 36 + 4 * 3 * 32 * 36) * 4; // 110592
    constexpr int SMEM_STEP = (4 * 4 * 32 * 36 + 64 * 516) * 4;        // 205824
    cudaFuncSetAttribute(gemm_big,
                         cudaFuncAttributeMaxDynamicSharedMemorySize, SMEM_BIG);
    cudaFuncSetAttribute(steps_k,
                         cudaFuncAttributeMaxDynamicSharedMemorySize, SMEM_STEP);

    // 1) conversions (av, W_ih, W_hh -> bf16) + flag reset
    conv_av_k<<<(BB * TT * HH / 8 + 255) / 256, 256>>>((const float4*)av,
                                                       BB * TT * HH / 8);
    conv_W_k<<<(HH * HH / 4 + 255) / 256, 256>>>(
        (const float4*)Wih, (const float4*)Whh, HH * HH / 4);

    // 2) Z = X @ W_ih^T + b_ih + b_hh   (bf16, group-private rings)
    gemm_big<<<dim3(8, 512), 256, SMEM_BIG>>>(bih, bhh);

    // 3) persistent recurrence (bf16), fully pair-decoupled chains
    steps_k<<<128, 256, SMEM_STEP>>>();

    // 4) head + loss (final h in g_hbf[1])
    head_k<<<128, 256>>>(Wout, bout);
    loss_k<<<1, BB>>>(y, (float*)d_out, out_size);
}

// round 17
// speedup vs baseline: 1.0318x; 1.0318x over previous
#include <cuda_runtime.h>
#include <cuda_bf16.h>
#include <cstdint>
#include <cstddef>

// ============================================================================
// RNN_4715874091371 — GB300 sm_103a (compute_103 PTX)
//   Z = X @ W_ih^T + (b_ih+b_hh)   bf16 GEMM 128x128/2CTA/warp 64x32 (R15)
//   h_t = tanh(Z_t + h_{t-1} @ W_hh^T)  persistent bf16 kernel, 128 CTAs,
//       CTA 128x64, W_hh resident, warp 32x32, pair-decoupled chains,
//       5-stage pair A rings (deeper cp.async overlap)
//   p = sigmoid(h @ W_out^T + b_out);  loss = BCE(p, y >= 1e-5)
// ============================================================================

static constexpr int TT = 64;
static constexpr int BB = 1024;
static constexpr int HH = 1024;

// ---------------- device scratch (allocation-free rule) --------------------
__device__ __nv_bfloat16 g_Xbf[(size_t)BB * TT * HH];    // av in bf16 (128MB)
__device__ __nv_bfloat16 g_Wihbf[(size_t)HH * HH];       // W_ih bf16
__device__ __nv_bfloat16 g_Whhbf[(size_t)HH * HH];       // W_hh bf16
__device__ float g_Z[(size_t)TT * BB * HH];               // [t][b][h] fp32
__device__ __nv_bfloat16 g_hbf[2][(size_t)BB * HH];       // ping-pong hidden
__device__ float g_p[BB];
__device__ unsigned g_pbars[8][4];                         // per-(group,pair)

#define DEVI __device__ __forceinline__

DEVI uint32_t smem_u32(const void* p) {
    uint32_t a;
    asm("{ .reg .u64 t; cvta.to.shared.u64 t, %1; cvt.u32.u64 %0, t; }"
        : "=r"(a) : "l"(p));
    return a;
}

#define CPA16(dst_b, src) \
    asm volatile("cp.async.cg.shared.global [%0], [%1], 16;" :: "r"(dst_b), "l"(src))
#define CPC()    asm volatile("cp.async.commit_group;" ::: "memory")
#define CPW2()   asm volatile("cp.async.wait_group 2;" ::: "memory")
#define CPW3()   asm volatile("cp.async.wait_group 3;" ::: "memory")
#define CPWALL() asm volatile("cp.async.wait_all;" ::: "memory")
#define BAR64(id)  asm volatile("bar.sync %0, 64;"  :: "r"(id) : "memory")

// bf16 m16n8k16: D += A*B
#define MMA_BF16(d, a, b)                                                       \
    asm("mma.sync.aligned.m16n8k16.row.col.f32.bf16.bf16.f32 "                  \
        "{%0,%1,%2,%3}, {%4,%5,%6,%7}, {%8,%9}, {%0,%1,%2,%3};"                 \
        : "+f"((d)[0]), "+f"((d)[1]), "+f"((d)[2]), "+f"((d)[3])                \
        : "r"((a)[0]), "r"((a)[1]), "r"((a)[2]), "r"((a)[3]),                   \
          "r"((b)[0]), "r"((b)[1]))

// ldmatrix x4: d[0..3] <- four 8x8 b16 matrices
#define LDSM4(d, addr)                                                          \
    asm volatile("ldmatrix.sync.aligned.m8n8.x4.shared.b16 {%0,%1,%2,%3}, [%4];"\
        : "=r"((d)[0]), "=r"((d)[1]), "=r"((d)[2]), "=r"((d)[3]) : "r"(addr))

// ============================================================================
// Big GEMM (bf16, R15 config): Z = Xbf @ Wihbf^T + (b_ih+b_hh). CTA tile
// 128x128, warp grid 2x4 (warp tile 64x32), K-chunk 64 halves, 16 chunks,
// 3 stages, 2 CTAs/SM, ldmatrix. grid(x = 8 n-tiles, y = 512 m-tiles).
// ============================================================================
__global__ __launch_bounds__(256, 2)
void gemm_big(const float* __restrict__ bih, const float* __restrict__ bhh)
{
    constexpr int SASZ = 128 * 36, SBSZ = 128 * 36, STG = SASZ + SBSZ; // words
    extern __shared__ __align__(16) uint32_t sm[];
    const uint32_t smb = smem_u32(sm);

    const int tid  = threadIdx.x;
    const int lane = tid & 31;
    const int wid  = tid >> 5;
    const int wm   = wid >> 2;             // 2 x 4 warp grid; warp tile 64x32
    const int wn   = wid & 3;
    const int n0   = blockIdx.x * 128;
    const int m0   = blockIdx.y * 128;

    const int lrA = lane & 15;
    const int whA = (lane >> 4) * 4;
    const int lrB = (lane & 7) | ((lane >> 4) << 3);
    const int wB  = ((lane >> 3) & 1) * 4;

    auto load_stage = [&](int c, int s) {
        const int kf = c * 64;                               // in halves
        const uint32_t ab = smb + (uint32_t)(s * STG) * 4;
        const uint32_t bb = ab + (uint32_t)SASZ * 4;
        #pragma unroll
        for (int i = 0; i < 4; ++i) {                        // A: 128 x 128B
            int e = tid + i * 256, r = e >> 3, j = e & 7;
            CPA16(ab + (uint32_t)(r * 36 + j * 4) * 4,
                  g_Xbf + (size_t)(m0 + r) * HH + kf + j * 8);
        }
        #pragma unroll
        for (int i = 0; i < 4; ++i) {                        // B: 128 x 128B
            int e = tid + i * 256, r = e >> 3, j = e & 7;
            CPA16(bb + (uint32_t)(r * 36 + j * 4) * 4,
                  g_Wihbf + (size_t)(n0 + r) * HH + kf + j * 8);
        }
    };

    #pragma unroll
    for (int c = 0; c < 3; ++c) { load_stage(c, c); CPC(); }

    float acc[4][4][4];
    #pragma unroll
    for (int mi = 0; mi < 4; ++mi)
        #pragma unroll
        for (int nf = 0; nf < 4; ++nf)
            #pragma unroll
            for (int j = 0; j < 4; ++j) acc[mi][nf][j] = 0.f;

    for (int c = 0; c < 16; ++c) {
        CPW2();
        __syncthreads();
        const uint32_t sA = smb + (uint32_t)((c % 3) * STG) * 4;
        const uint32_t sB = sA + (uint32_t)SASZ * 4;
        #pragma unroll
        for (int ks = 0; ks < 4; ++ks) {                     // k16 per MMA
            uint32_t a[4][4];
            #pragma unroll
            for (int mi = 0; mi < 4; ++mi)
                LDSM4(a[mi], sA + (uint32_t)((wm * 64 + mi * 16 + lrA) * 36
                                             + ks * 8 + whA) * 4);
            uint32_t b[4][2];
            #pragma unroll
            for (int nfp = 0; nfp < 2; ++nfp)
                LDSM4((&b[2 * nfp][0]),
                      sB + (uint32_t)((wn * 32 + nfp * 16 + lrB) * 36
                                      + ks * 8 + wB) * 4);
            #pragma unroll
            for (int mi = 0; mi < 4; ++mi)
                #pragma unroll
                for (int nf = 0; nf < 4; ++nf)
                    MMA_BF16(acc[mi][nf], a[mi], b[nf]);
        }
        __syncthreads();
        if (c + 3 < 16) load_stage(c + 3, c % 3);
        CPC();
    }

    // epilogue: + biases, scatter to g_Z[t][b][n]  (m = b*64 + t)
    const int arow = lane >> 2, q = lane & 3;
    #pragma unroll
    for (int mi = 0; mi < 4; ++mi) {
        const int r0 = m0 + wm * 64 + mi * 16 + arow;
        #pragma unroll
        for (int nf = 0; nf < 4; ++nf) {
            const int cg = n0 + wn * 32 + nf * 8 + q * 2;
            const float bsum0 = bih[cg] + bhh[cg];
            const float bsum1 = bih[cg + 1] + bhh[cg + 1];
            #pragma unroll
            for (int half = 0; half < 2; ++half) {
                const int r = r0 + half * 8;
                float2 o;
                o.x = acc[mi][nf][half * 2 + 0] + bsum0;
                o.y = acc[mi][nf][half * 2 + 1] + bsum1;
                const int b = r >> 6, t = r & 63;
                *(float2*)(g_Z + ((size_t)t * BB + b) * HH + cg) = o;
            }
        }
    }
}

// ============================================================================
// Persistent steps (bf16): 128 CTAs (8 m-groups x 16 n-tiles), CTA 128x64,
// warp grid 4x2 (warp tile 32x32). W_hh resident in smem. Four warp PAIRS
// (wm) each own: a private 5-STAGE A ring, a named pair barrier, and a
// per-(group,pair) flag chain — fully independent across the recurrence.
// ============================================================================
__global__ __launch_bounds__(256, 1)
void steps_k()
{
    constexpr int NST  = 5;                        // A ring stages
    constexpr int APST = 32 * 36;                  // words per pair A stage
    constexpr int BOFF = 4 * NST * APST;           // B base (word offset)
    constexpr int RSB  = 516;                      // B row stride (words)
    extern __shared__ __align__(16) uint32_t sm[];
    const uint32_t smb = smem_u32(sm);

    const int tid  = threadIdx.x;
    const int lane = tid & 31;
    const int wid  = tid >> 5;
    const int wm   = wid >> 1;             // pair id 0..3; warp tile 32x32
    const int wn   = wid & 1;
    const int pt   = tid & 63;             // pair-local thread 0..63
    const int mg   = blockIdx.x >> 4;      // m-group 0..7
    const int m0   = mg * 128;
    const int n0   = (blockIdx.x & 15) * 64;
    const uint32_t pbase = smb + (uint32_t)(wm * NST * APST) * 4;
    unsigned* const myflag = &g_pbars[mg][wm];

    // ---- load resident B = W_hh rows n0..n0+63, full K (CTA-wide) ----
    #pragma unroll
    for (int i = 0; i < 32; ++i) {
        int e = tid + i * 256, r = e >> 7, j = e & 127;
        CPA16(smb + (uint32_t)(BOFF + r * RSB + j * 4) * 4,
              g_Whhbf + (size_t)(n0 + r) * HH + j * 8);
    }
    CPC();
    CPWALL();
    __syncthreads();                       // one-time: B resident for all pairs

    // ---- t = 0: h0 = tanh(Z_0) on this pair's band (32 x 64) ----
    for (int e = pt; e < 32 * 64; e += 64) {
        int r = e >> 6, c = e & 63;
        size_t idx = (size_t)(m0 + wm * 32 + r) * HH + n0 + c;
        g_hbf[0][idx] = __float2bfloat16_rn(tanhf(g_Z[idx]));
    }
    BAR64(1 + wm);
    if (pt == 0) { __threadfence(); atomicAdd(myflag, 1); }

    const int arow = lane >> 2, q = lane & 3;
    const int lrA = lane & 15;
    const int whA = (lane >> 4) * 4;
    const int lrB = (lane & 7) | ((lane >> 4) << 3);
    const int wB  = ((lane >> 3) & 1) * 4;

    for (int t = 1; t < TT; ++t) {
        const __nv_bfloat16* __restrict__ Asrc = g_hbf[(t - 1) & 1];
        __nv_bfloat16*       __restrict__ out  = g_hbf[t & 1];
        const float*         __restrict__ Zt   = g_Z + (size_t)t * BB * HH;

        // Z prefetch (independent of h): hide behind flag wait
        float2 zf[2][4][2];
        #pragma unroll
        for (int mi = 0; mi < 2; ++mi)
            #pragma unroll
            for (int nf = 0; nf < 4; ++nf) {
                const int cg = n0 + wn * 32 + nf * 8 + q * 2;
                #pragma unroll
                for (int half = 0; half < 2; ++half) {
                    const int r = m0 + wm * 32 + mi * 16 + arow + half * 8;
                    zf[mi][nf][half] = *(const float2*)(Zt + (size_t)r * HH + cg);
                }
            }

        // per-(group,pair) chain: 16 CTA-pairs wrote this band of h_{t-1}
        if (pt == 0) {
            const unsigned tgt = 16u * (unsigned)t;
            while (*(volatile unsigned*)myflag < tgt) __nanosleep(32);
            __threadfence();
        }
        BAR64(1 + wm);

        // pair A stage loader: chunk c (64 halves) of this pair's 32 rows
        auto load_stage = [&](int c, int s) {
            const int kf = c * 64;
            const uint32_t ab = pbase + (uint32_t)(s * APST) * 4;
            #pragma unroll
            for (int i = 0; i < 4; ++i) {                    // 32 rows x 128B
                int e = pt + i * 64, r = e >> 3, j = e & 7;
                CPA16(ab + (uint32_t)(r * 36 + j * 4) * 4,
                      Asrc + (size_t)(m0 + wm * 32 + r) * HH + kf + j * 8);
            }
        };

        // prologue: 4 chunks in flight
        #pragma unroll
        for (int c = 0; c < 4; ++c) { load_stage(c, c); CPC(); }

        float acc[2][4][4];
        #pragma unroll
        for (int mi = 0; mi < 2; ++mi)
            #pragma unroll
            for (int nf = 0; nf < 4; ++nf)
                #pragma unroll
                for (int j = 0; j < 4; ++j) acc[mi][nf][j] = 0.f;

        for (int c = 0; c < 16; ++c) {
            CPW3();                       // own chunk c landed (<=3 pending)
            BAR64(1 + wm);                // pair: both warps done with old slot
            if (c + 4 < 16) load_stage(c + 4, (c + 4) % NST);
            CPC();
            const uint32_t sA = pbase + (uint32_t)((c % NST) * APST) * 4;
            #pragma unroll
            for (int ks = 0; ks < 4; ++ks) {                 // k16 per MMA
                uint32_t a[2][4];
                #pragma unroll
                for (int mi = 0; mi < 2; ++mi)
                    LDSM4(a[mi], sA + (uint32_t)((mi * 16 + lrA) * 36
                                                 + ks * 8 + whA) * 4);
                uint32_t b[4][2];
                #pragma unroll
                for (int nfp = 0; nfp < 2; ++nfp)
                    LDSM4((&b[2 * nfp][0]),
                          smb + (uint32_t)(BOFF
                                + (wn * 32 + nfp * 16 + lrB) * RSB
                                + c * 32 + ks * 8 + wB) * 4);
                #pragma unroll
                for (int mi = 0; mi < 2; ++mi)
                    #pragma unroll
                    for (int nf = 0; nf < 4; ++nf)
                        MMA_BF16(acc[mi][nf], a[mi], b[nf]);
            }
        }

        // epilogue: tanh(acc + Z_t) -> bf16 h[t&1] (own band only)
        #pragma unroll
        for (int mi = 0; mi < 2; ++mi)
            #pragma unroll
            for (int nf = 0; nf < 4; ++nf) {
                const int cg = n0 + wn * 32 + nf * 8 + q * 2;
                #pragma unroll
                for (int half = 0; half < 2; ++half) {
                    const int r = m0 + wm * 32 + mi * 16 + arow + half * 8;
                    float ox = tanhf(acc[mi][nf][half * 2 + 0] + zf[mi][nf][half].x);
                    float oy = tanhf(acc[mi][nf][half * 2 + 1] + zf[mi][nf][half].y);
                    __nv_bfloat162 o2 = __floats2bfloat162_rn(ox, oy);
                    *(__nv_bfloat162*)(out + (size_t)r * HH + cg) = o2;
                }
            }
        BAR64(1 + wm);
        if (pt == 0) { __threadfence(); atomicAdd(myflag, 1); }
    }
}

// ----------------------------- small kernels --------------------------------
__global__ void conv_av_k(const float4* __restrict__ av, int n8) {
    int i = blockIdx.x * blockDim.x + threadIdx.x;       // 8 floats per thread
    if (i < n8) {
        float4 a = av[2 * i], b = av[2 * i + 1];
        __nv_bfloat162 p0 = __floats2bfloat162_rn(a.x, a.y);
        __nv_bfloat162 p1 = __floats2bfloat162_rn(a.z, a.w);
        __nv_bfloat162 p2 = __floats2bfloat162_rn(b.x, b.y);
        __nv_bfloat162 p3 = __floats2bfloat162_rn(b.z, b.w);
        uint4 o = make_uint4(*(uint32_t*)&p0, *(uint32_t*)&p1,
                             *(uint32_t*)&p2, *(uint32_t*)&p3);
        ((uint4*)g_Xbf)[i] = o;
    }
}

__global__ void conv_W_k(const float4* __restrict__ wih,
                         const float4* __restrict__ whh, int n4) {
    int i = blockIdx.x * blockDim.x + threadIdx.x;
    if (i < 32) ((unsigned*)g_pbars)[i] = 0;              // reset flag chains
    if (i < n4) {
        float4 a = wih[i];
        __nv_bfloat162 p0 = __floats2bfloat162_rn(a.x, a.y);
        __nv_bfloat162 p1 = __floats2bfloat162_rn(a.z, a.w);
        ((uint2*)g_Wihbf)[i] = make_uint2(*(uint32_t*)&p0, *(uint32_t*)&p1);
        float4 b = whh[i];
        __nv_bfloat162 q0 = __floats2bfloat162_rn(b.x, b.y);
        __nv_bfloat162 q1 = __floats2bfloat162_rn(b.z, b.w);
        ((uint2*)g_Whhbf)[i] = make_uint2(*(uint32_t*)&q0, *(uint32_t*)&q1);
    }
}

__global__ void head_k(const float* __restrict__ Wout,
                       const float* __restrict__ bout) {
    int wid = threadIdx.x >> 5, lane = threadIdx.x & 31;
    int row = blockIdx.x * 8 + wid;
    const __nv_bfloat162* hr =
        (const __nv_bfloat162*)(g_hbf[1] + (size_t)row * HH);
    const float2* wr = (const float2*)Wout;
    float s = 0.f;
    for (int i = lane; i < HH / 2; i += 32) {
        float2 hv = __bfloat1622float2(hr[i]);
        float2 wv = wr[i];
        s += hv.x * wv.x + hv.y * wv.y;
    }
    #pragma unroll
    for (int o = 16; o; o >>= 1) s += __shfl_xor_sync(0xFFFFFFFFu, s, o);
    if (lane == 0) g_p[row] = 1.f / (1.f + expf(-(s + bout[0])));
}

__global__ void loss_k(const float* __restrict__ y, float* __restrict__ out,
                       int out_size) {
    __shared__ float red[32];
    int tid = threadIdx.x;                                // 1024 threads
    float pv = g_p[tid];
    float yb = (y[tid] >= 1e-5f) ? 1.f : 0.f;
    float term = yb * fmaxf(logf(pv), -100.f)
               + (1.f - yb) * fmaxf(log1pf(-pv), -100.f);
    #pragma unroll
    for (int o = 16; o; o >>= 1) term += __shfl_xor_sync(0xFFFFFFFFu, term, o);
    if ((tid & 31) == 0) red[tid >> 5] = term;
    __syncthreads();
    if (tid < 32) {
        float v = red[tid];
        #pragma unroll
        for (int o = 16; o; o >>= 1) v += __shfl_xor_sync(0xFFFFFFFFu, v, o);
        if (tid == 0 && out_size != BB) out[0] = -v / (float)BB;
    }
    if (out_size >= 1 + BB)      out[1 + tid] = pv;
    else if (out_size == BB)     out[tid] = pv;
    for (int i = 1 + BB + tid; i < out_size; i += BB) out[i] = 0.f;
}

// ------------------------------- launcher -----------------------------------
extern "C" void kernel_launch(void* const* d_in, const int* in_sizes, int n_in,
                              void* d_out, int out_size) {
    const float* av   = (const float*)d_in[3];
    const float* y    = (const float*)d_in[4];
    const float* Wih  = (const float*)d_in[5];
    const float* bih  = (const float*)d_in[6];
    const float* Whh  = (const float*)d_in[7];
    const float* bhh  = (const float*)d_in[8];
    const float* Wout = (const float*)d_in[9];
    const float* bout = (const float*)d_in[10];
    (void)in_sizes; (void)n_in;

    constexpr int SMEM_BIG  = 3 * (128 * 36 + 128 * 36) * 4;       // 110592 B
    constexpr int SMEM_STEP = (4 * 5 * 32 * 36 + 64 * 516) * 4;    // 224256 B
    cudaFuncSetAttribute(gemm_big,
                         cudaFuncAttributeMaxDynamicSharedMemorySize, SMEM_BIG);
    cudaFuncSetAttribute(steps_k,
                         cudaFuncAttributeMaxDynamicSharedMemorySize, SMEM_STEP);

    // 1) conversions (av, W_ih, W_hh -> bf16) + flag reset
    conv_av_k<<<(BB * TT * HH / 8 + 255) / 256, 256>>>((const float4*)av,
                                                       BB * TT * HH / 8);
    conv_W_k<<<(HH * HH / 4 + 255) / 256, 256>>>(
        (const float4*)Wih, (const float4*)Whh, HH * HH / 4);

    // 2) Z = X @ W_ih^T + b_ih + b_hh   (bf16, 128x128, 2 CTAs/SM)
    gemm_big<<<dim3(8, 512), 256, SMEM_BIG>>>(bih, bhh);

    // 3) persistent recurrence (bf16), pair-decoupled, 5-stage rings
    steps_k<<<128, 256, SMEM_STEP>>>();

    // 4) head + loss (final h in g_hbf[1])
    head_k<<<128, 256>>>(Wout, bout);
    loss_k<<<1, BB>>>(y, (float*)d_out, out_size);
}